// round 10
// baseline (speedup 1.0000x reference)
#include <cuda_runtime.h>
#include <math.h>
#include <stdint.h>

// MT 1D forward + loss — diagonalized projective q-form recursion with a
// HARD two-phase pipeline per 8 steps, staged through shared memory via
// inline-asm st.shared/ld.shared so the compiler CANNOT re-fuse the
// coefficient chains back into the state chain (which it did in R4/R8/R9,
// leaving the kernel serial-latency bound at ~71 cyc/step).
//   Step (scalar p dropped — cancels in (S+D)/(S-D)):
//     T = E*D ; S' = S - q*T ; D' = q*S - T            (8 FMA ops)
//     E = exp(-arg)(cos arg - i sin arg), arg = sqrt2*t*sqrt(omega*mu/rho)
//     q = (w-1)/(w+1), w = sqrt(rho_j/rho_{j-1})
//   Phase A: 8 independent coef sets (LDS+3 MUFU each, pipelined) -> smem.
//   Phase B: 8 LDS.128 back-to-back, then 8 serial applies (chain ~12 cyc).
//   New floor = MUFU rt: 3 MUFU/step * 8 cyc = 24 cyc/step (was ~71).
// Exact pow2 renorm every 8 steps (cancels in the S/D ratio).
// Loss reduction fused via fence + atomic ticket (reset for graph replay).

#define MU_F 1.2566370614359173e-6f
#define TWO_PI_F 6.283185307179586f
#define SQRT2_F 1.4142135623730951f
#define RAD2DEG_F 57.29577951308232f
#define NLOG2E_F (-1.4426950408889634f)

static __device__ float2 g_part[1024];
static __device__ unsigned g_ticket;   // zero-init; last block resets to 0

__device__ __forceinline__ float pow2_scale(float m0)
{
    float m = fmaxf(m0, 1e-30f);
    unsigned eb = __float_as_uint(m) & 0x7f800000u;
    return __uint_as_float(0x7f000000u - eb);
}

__global__ __launch_bounds__(128, 1) void mt_fused(
    const float* __restrict__ rho, const float* __restrict__ thick,
    const float* __restrict__ freq, const float* __restrict__ obs_r,
    const float* __restrict__ obs_p, float* __restrict__ out,
    int nz, int nf, float invnf)
{
    // Layer j at sLs[j+1]: x = sqrt2*t/sqrt(rho), y = -log2e*x, z = q
    __shared__ float4 sLs[513];
    __shared__ float4 sC[8][128];      // staged coefs: [k][tid] (conflict-free)
    __shared__ float s_y0, s_rho0;
    __shared__ int s_last;

    const int tid = threadIdx.x;
    for (int j = tid; j < nz - 1; j += blockDim.x) {
        float r = rho[j];
        float T = SQRT2_F * thick[j] * rsqrtf(r);
        float w = (j > 0) ? sqrtf(r / rho[j - 1]) : 1.0f;
        float q = (w - 1.f) / (w + 1.f);
        sLs[j + 1] = make_float4(T, NLOG2E_F * T, q, 0.f);
    }
    if (tid == 0) {
        sLs[0] = make_float4(0.f, 0.f, 0.f, 0.f);
        s_y0 = sqrtf(rho[nz - 1] / rho[nz - 2]);
        s_rho0 = rho[0];
    }
    __syncthreads();

    // smem byte address of this thread's staging slot k
    uint32_t cbase = (uint32_t)__cvta_generic_to_shared(&sC[0][tid]);
    const uint32_t CSTRIDE = 128u * 16u;   // bytes between k slots

    const int i = blockIdx.x * blockDim.x + tid;
    float t1 = 0.f, t2 = 0.f;
    if (i < nf) {
        const float omu = TWO_PI_F * freq[i] * MU_F;
        const float s = sqrtf(omu);
        const float y0 = s_y0;
        float Sre = y0 + 1.f, Sim = 0.f;
        float Dre = y0 - 1.f, Dim = 0.f;

        const int nL = nz - 1;         // steps j = nL-1 .. 0
        int j = nL - 1;
        int rem = nL & 7;              // peel so bulk is blocks of 8
        #pragma unroll 1
        for (int k = 0; k < rem; ++k, --j) {
            float4 L = sLs[j + 1];
            float arg = s * L.x;
            float e; asm("ex2.approx.ftz.f32 %0, %1;" : "=f"(e) : "f"(s * L.y));
            float sn, cs; __sincosf(arg, &sn, &cs);
            float ec = e * cs, es = e * sn;
            float Tre = ec * Dre + es * Dim;
            float Tim = ec * Dim - es * Dre;
            float nSre = Sre - L.z * Tre;
            float nSim = Sim - L.z * Tim;
            float nDre = L.z * Sre - Tre;
            float nDim = L.z * Sim - Tim;
            Sre = nSre; Sim = nSim; Dre = nDre; Dim = nDim;
        }
        {
            float sc = pow2_scale(fmaxf(fmaxf(fabsf(Sre), fabsf(Sim)),
                                        fmaxf(fabsf(Dre), fabsf(Dim))));
            Sre *= sc; Sim *= sc; Dre *= sc; Dim *= sc;
        }

        #pragma unroll 1
        while (j >= 7) {
            // ---- Phase A: 8 independent coefficient sets -> smem ----
            #pragma unroll
            for (int k = 0; k < 8; ++k) {
                float4 L = sLs[j + 1 - k];
                float arg = s * L.x;
                float e; asm("ex2.approx.ftz.f32 %0, %1;"
                             : "=f"(e) : "f"(s * L.y));
                float sn, cs; __sincosf(arg, &sn, &cs);
                float ec = e * cs, es = e * sn;
                asm volatile("st.shared.v4.f32 [%0], {%1, %2, %3, %4};"
                             :: "r"(cbase + (uint32_t)k * CSTRIDE),
                                "f"(ec), "f"(es), "f"(L.z), "f"(0.f)
                             : "memory");
            }
            // ---- Phase B: load all 8, then apply serially ----
            float cx[8], cy[8], cz[8];
            #pragma unroll
            for (int k = 0; k < 8; ++k) {
                float dummy;
                asm volatile("ld.shared.v4.f32 {%0, %1, %2, %3}, [%4];"
                             : "=f"(cx[k]), "=f"(cy[k]), "=f"(cz[k]),
                               "=f"(dummy)
                             : "r"(cbase + (uint32_t)k * CSTRIDE));
            }
            #pragma unroll
            for (int k = 0; k < 8; ++k) {
                float Tre = cx[k] * Dre + cy[k] * Dim;
                float Tim = cx[k] * Dim - cy[k] * Dre;
                float nSre = Sre - cz[k] * Tre;
                float nSim = Sim - cz[k] * Tim;
                float nDre = cz[k] * Sre - Tre;
                float nDim = cz[k] * Sim - Tim;
                Sre = nSre; Sim = nSim; Dre = nDre; Dim = nDim;
            }
            j -= 8;
            float sc = pow2_scale(fmaxf(fmaxf(fabsf(Sre), fabsf(Sim)),
                                        fmaxf(fabsf(Dre), fabsf(Dim))));
            Sre *= sc; Sim *= sc; Dre *= sc; Dim *= sc;
        }

        // y = (S+D)/(S-D); Z = y*Z_L0, |Z_L0|^2 = omu*rho0, arg(Z_L0)=45deg
        float nre = Sre + Dre, nim = Sim + Dim;
        float dre = Sre - Dre, dim = Sim - Dim;
        float dd = dre * dre + dim * dim;
        float app_res = s_rho0 * (nre * nre + nim * nim) / dd;
        float yr = nre * dre + nim * dim;
        float yi = nim * dre - nre * dim;
        float dl = log10f(app_res) - log10f(obs_r[i]);
        t1 = dl * dl;
        float ph = atan2f(yi, yr) * RAD2DEG_F + 45.0f;
        float dp = ph - obs_p[i];
        t2 = dp * dp;
    }

    // deterministic block reduction
    float x = t1, y = t2;
    #pragma unroll
    for (int o = 16; o > 0; o >>= 1) {
        x += __shfl_down_sync(0xffffffffu, x, o);
        y += __shfl_down_sync(0xffffffffu, y, o);
    }
    __shared__ float2 ws[4];
    int w = tid >> 5, l = tid & 31;
    if (l == 0) ws[w] = make_float2(x, y);
    __syncthreads();
    if (w == 0) {
        float2 vv = (l < 4) ? ws[l] : make_float2(0.f, 0.f);
        #pragma unroll
        for (int o = 2; o > 0; o >>= 1) {
            vv.x += __shfl_down_sync(0xffffffffu, vv.x, o);
            vv.y += __shfl_down_sync(0xffffffffu, vv.y, o);
        }
        if (l == 0) g_part[blockIdx.x] = vv;
    }

    // last-block final reduction (fence + ticket; reset keeps replays valid)
    __threadfence();
    if (tid == 0) {
        unsigned t = atomicAdd(&g_ticket, 1u);
        s_last = (t == gridDim.x - 1u);
    }
    __syncthreads();
    if (s_last) {
        int nb = gridDim.x;
        float fx = 0.f, fy = 0.f;
        for (int b = tid; b < nb; b += blockDim.x) {
            float2 p = g_part[b];
            fx += p.x; fy += p.y;
        }
        #pragma unroll
        for (int o = 16; o > 0; o >>= 1) {
            fx += __shfl_down_sync(0xffffffffu, fx, o);
            fy += __shfl_down_sync(0xffffffffu, fy, o);
        }
        __shared__ float2 ws2[4];
        if (l == 0) ws2[w] = make_float2(fx, fy);
        __syncthreads();
        if (tid == 0) {
            float gx = 0.f, gy = 0.f;
            int nw = (int)blockDim.x >> 5;
            for (int q = 0; q < nw; ++q) { gx += ws2[q].x; gy += ws2[q].y; }
            float lr = gx * invnf;
            float lp = gy * invnf;
            out[0] = lr + 10.f * lp;
            out[1] = lr;
            out[2] = lp;
            g_ticket = 0u;   // reset for next graph replay
        }
    }
}

extern "C" void kernel_launch(void* const* d_in, const int* in_sizes, int n_in,
                              void* d_out, int out_size)
{
    const float* rho    = (const float*)d_in[0];
    const float* thick  = (const float*)d_in[1];
    const float* freq   = (const float*)d_in[2];
    const float* obs_r  = (const float*)d_in[3];
    const float* obs_p  = (const float*)d_in[4];
    int nz = in_sizes[0];
    int nf = in_sizes[2];
    int blocks = (nf + 127) / 128;
    if (blocks > 1024) blocks = 1024;  // g_part capacity (nf=16384 -> 128)
    mt_fused<<<blocks, 128>>>(rho, thick, freq, obs_r, obs_p,
                              (float*)d_out, nz, nf, 1.f / (float)nf);
}

// round 11
// speedup vs baseline: 1.5100x; 1.5100x over previous
#include <cuda_runtime.h>
#include <math.h>
#include <stdint.h>

// MT 1D forward + loss — diagonalized projective q-form recursion.
//   Step (scalar p dropped — cancels in (S+D)/(S-D)):
//     T = E*D ; S' = S - q*T ; D' = q*S - T
//     E = exp(-arg)(cos arg - i sin arg), arg = sqrt2*t*sqrt(omega*mu/rho)
//     q = (w-1)/(w+1), w = sqrt(rho_j/rho_{j-1})
// R5-R10 established the bottleneck is the per-SM transcendental (XU) pipe:
// time tracks trig/exp warp-op count per SM (~6 cyc/op, shared SM-wide),
// invariant to warp count and FMA count. This version moves exp(-arg) OFF
// the XU pipe onto the idle FMA pipe (2^x via round-trick + degree-6 poly,
// exact-bias exponent scale on the ALU pipe), keeping only sin/cos on MUFU:
// XU per SM drops 3060 -> 2040 ops, FMA rises to ~25 ops/step — balanced.
// Exact pow2 renorm every 8 steps (cancels in the S/D ratio).
// Loss reduction fused via fence + atomic ticket (reset for graph replay).

#define MU_F 1.2566370614359173e-6f
#define TWO_PI_F 6.283185307179586f
#define SQRT2_F 1.4142135623730951f
#define RAD2DEG_F 57.29577951308232f
#define NLOG2E_F (-1.4426950408889634f)

static __device__ float2 g_part[1024];
static __device__ unsigned g_ticket;   // zero-init; last block resets to 0

__device__ __forceinline__ float pow2_scale(float m0)
{
    float m = fmaxf(m0, 1e-30f);
    unsigned eb = __float_as_uint(m) & 0x7f800000u;
    return __uint_as_float(0x7f000000u - eb);
}

// 2^x on the FMA pipe, x in [-126, 0]. Round-to-nearest-int via the
// 1.5*2^23 bias trick; degree-6 poly on r in [-0.5, 0.5]; exponent scale
// assembled with integer ops (ALU pipe). Max rel err ~1e-7.
__device__ __forceinline__ float exp2_fma(float x)
{
    const float C = 12582912.0f;           // 1.5 * 2^23
    float t  = x + C;                      // low mantissa bits hold round(x)
    float nf = t - C;                      // round(x) as float (RN)
    float r  = x - nf;                     // r in [-0.5, 0.5]
    // (ibits<<23) + 0x3F800000 == (n+127)<<23  (bias bits of C shift out)
    float sc = __int_as_float((__float_as_int(t) << 23) + 0x3F800000);
    float p = 1.535336188319500e-4f;
    p = fmaf(p, r, 1.339887440266574e-3f);
    p = fmaf(p, r, 9.618437357674640e-3f);
    p = fmaf(p, r, 5.550332471162809e-2f);
    p = fmaf(p, r, 2.402264791363012e-1f);
    p = fmaf(p, r, 6.931472028550421e-1f);
    p = fmaf(p, r, 1.0f);
    return p * sc;
}

__global__ __launch_bounds__(128, 1) void mt_fused(
    const float* __restrict__ rho, const float* __restrict__ thick,
    const float* __restrict__ freq, const float* __restrict__ obs_r,
    const float* __restrict__ obs_p, float* __restrict__ out,
    int nz, int nf, float invnf)
{
    // Layer j at sLs[j+1]: x = sqrt2*t/sqrt(rho), y = -log2e*x, z = q
    __shared__ float4 sLs[513];
    __shared__ float s_y0, s_rho0;
    __shared__ int s_last;

    const int tid = threadIdx.x;
    for (int j = tid; j < nz - 1; j += blockDim.x) {
        float r = rho[j];
        float T = SQRT2_F * thick[j] * rsqrtf(r);
        float w = (j > 0) ? sqrtf(r / rho[j - 1]) : 1.0f;
        float q = (w - 1.f) / (w + 1.f);
        sLs[j + 1] = make_float4(T, NLOG2E_F * T, q, 0.f);
    }
    if (tid == 0) {
        sLs[0] = make_float4(0.f, 0.f, 0.f, 0.f);
        s_y0 = sqrtf(rho[nz - 1] / rho[nz - 2]);
        s_rho0 = rho[0];
    }
    __syncthreads();

    const int i = blockIdx.x * blockDim.x + tid;
    float t1 = 0.f, t2 = 0.f;
    if (i < nf) {
        const float omu = TWO_PI_F * freq[i] * MU_F;
        const float s = sqrtf(omu);
        const float y0 = s_y0;
        float Sre = y0 + 1.f, Sim = 0.f;
        float Dre = y0 - 1.f, Dim = 0.f;

        const int nL = nz - 1;         // steps j = nL-1 .. 0
        int j = nL - 1;
        int rem = nL & 7;              // peel so bulk is blocks of 8
        #pragma unroll 1
        for (int k = 0; k < rem; ++k, --j) {
            float4 L = sLs[j + 1];
            float arg = s * L.x;
            float e = exp2_fma(s * L.y);           // exp(-arg), FMA pipe
            float sn, cs; __sincosf(arg, &sn, &cs);
            float ec = e * cs, es = e * sn;        // E = ec - i*es
            float Tre = ec * Dre + es * Dim;
            float Tim = ec * Dim - es * Dre;
            float nSre = Sre - L.z * Tre;
            float nSim = Sim - L.z * Tim;
            float nDre = L.z * Sre - Tre;
            float nDim = L.z * Sim - Tim;
            Sre = nSre; Sim = nSim; Dre = nDre; Dim = nDim;
        }
        {
            float sc = pow2_scale(fmaxf(fmaxf(fabsf(Sre), fabsf(Sim)),
                                        fmaxf(fabsf(Dre), fabsf(Dim))));
            Sre *= sc; Sim *= sc; Dre *= sc; Dim *= sc;
        }

        #pragma unroll 1
        while (j >= 7) {
            #pragma unroll
            for (int k = 0; k < 8; ++k) {
                float4 L = sLs[j + 1 - k];
                float arg = s * L.x;
                float e = exp2_fma(s * L.y);       // exp(-arg), FMA pipe
                float sn, cs; __sincosf(arg, &sn, &cs);
                float ec = e * cs, es = e * sn;
                float Tre = ec * Dre + es * Dim;
                float Tim = ec * Dim - es * Dre;
                float nSre = Sre - L.z * Tre;
                float nSim = Sim - L.z * Tim;
                float nDre = L.z * Sre - Tre;
                float nDim = L.z * Sim - Tim;
                Sre = nSre; Sim = nSim; Dre = nDre; Dim = nDim;
            }
            j -= 8;
            float sc = pow2_scale(fmaxf(fmaxf(fabsf(Sre), fabsf(Sim)),
                                        fmaxf(fabsf(Dre), fabsf(Dim))));
            Sre *= sc; Sim *= sc; Dre *= sc; Dim *= sc;
        }

        // y = (S+D)/(S-D); Z = y*Z_L0, |Z_L0|^2 = omu*rho0, arg(Z_L0)=45deg
        float nre = Sre + Dre, nim = Sim + Dim;
        float dre = Sre - Dre, dim = Sim - Dim;
        float dd = dre * dre + dim * dim;
        float app_res = s_rho0 * (nre * nre + nim * nim) / dd;
        float yr = nre * dre + nim * dim;
        float yi = nim * dre - nre * dim;
        float dl = log10f(app_res) - log10f(obs_r[i]);
        t1 = dl * dl;
        float ph = atan2f(yi, yr) * RAD2DEG_F + 45.0f;
        float dp = ph - obs_p[i];
        t2 = dp * dp;
    }

    // deterministic block reduction
    float x = t1, y = t2;
    #pragma unroll
    for (int o = 16; o > 0; o >>= 1) {
        x += __shfl_down_sync(0xffffffffu, x, o);
        y += __shfl_down_sync(0xffffffffu, y, o);
    }
    __shared__ float2 ws[4];
    int w = tid >> 5, l = tid & 31;
    if (l == 0) ws[w] = make_float2(x, y);
    __syncthreads();
    if (w == 0) {
        float2 vv = (l < 4) ? ws[l] : make_float2(0.f, 0.f);
        #pragma unroll
        for (int o = 2; o > 0; o >>= 1) {
            vv.x += __shfl_down_sync(0xffffffffu, vv.x, o);
            vv.y += __shfl_down_sync(0xffffffffu, vv.y, o);
        }
        if (l == 0) g_part[blockIdx.x] = vv;
    }

    // last-block final reduction (fence + ticket; reset keeps replays valid)
    __threadfence();
    if (tid == 0) {
        unsigned t = atomicAdd(&g_ticket, 1u);
        s_last = (t == gridDim.x - 1u);
    }
    __syncthreads();
    if (s_last) {
        int nb = gridDim.x;
        float fx = 0.f, fy = 0.f;
        for (int b = tid; b < nb; b += blockDim.x) {
            float2 p = g_part[b];
            fx += p.x; fy += p.y;
        }
        #pragma unroll
        for (int o = 16; o > 0; o >>= 1) {
            fx += __shfl_down_sync(0xffffffffu, fx, o);
            fy += __shfl_down_sync(0xffffffffu, fy, o);
        }
        __shared__ float2 ws2[4];
        if (l == 0) ws2[w] = make_float2(fx, fy);
        __syncthreads();
        if (tid == 0) {
            float gx = 0.f, gy = 0.f;
            int nw = (int)blockDim.x >> 5;
            for (int q = 0; q < nw; ++q) { gx += ws2[q].x; gy += ws2[q].y; }
            float lr = gx * invnf;
            float lp = gy * invnf;
            out[0] = lr + 10.f * lp;
            out[1] = lr;
            out[2] = lp;
            g_ticket = 0u;   // reset for next graph replay
        }
    }
}

extern "C" void kernel_launch(void* const* d_in, const int* in_sizes, int n_in,
                              void* d_out, int out_size)
{
    const float* rho    = (const float*)d_in[0];
    const float* thick  = (const float*)d_in[1];
    const float* freq   = (const float*)d_in[2];
    const float* obs_r  = (const float*)d_in[3];
    const float* obs_p  = (const float*)d_in[4];
    int nz = in_sizes[0];
    int nf = in_sizes[2];
    int blocks = (nf + 127) / 128;
    if (blocks > 1024) blocks = 1024;  // g_part capacity (nf=16384 -> 128)
    mt_fused<<<blocks, 128>>>(rho, thick, freq, obs_r, obs_p,
                              (float*)d_out, nz, nf, 1.f / (float)nf);
}